// round 13
// baseline (speedup 1.0000x reference)
#include <cuda_runtime.h>
#include <cstdint>

// SigJoin (Chen's identity), D=8, M=6, BATCH=128, SIGLEN=299592.
// z_k[j] = x_k[j] + A(j>>3) * y[j&7];  A constant per aligned 8-group.
// One thread per 8-group (2x float4, fully coalesced). Identical to the best
// R4 kernel except the x stream uses default-policy loads: the low levels of
// x are re-read as prefix operands by higher-level threads, so evict-first
// (__ldcs) on x was evicting its own prefix working set from L2.

#define SJ_D      8
#define SJ_SIGLEN 299592
#define SJ_BATCH  128
#define SJ_GROUPS (SJ_SIGLEN / 8)   // 37449 groups per row

__device__ __forceinline__ float sj_invf(int n) {
    const float t[7] = {0.f, 1.f, 0.5f, 1.f/6.f, 1.f/24.f, 1.f/120.f, 1.f/720.f};
    return t[n];
}

__device__ __forceinline__ int sj_loff(int i) {
    const int t[7] = {0, 0, 8, 72, 584, 4680, 37448};
    return t[i];
}

// A = sum_{i=0}^{K-1} X_i * P_i * invf(K-i),  P_i = prod_{t=i}^{K-2} y[d_t].
template <int K>
__device__ __forceinline__ float sj_chenA(const float* __restrict__ xr,
                                          const float* __restrict__ ys,
                                          int r) {
    float A = 0.f;
    float P = 1.f;
    int idx = r;
#pragma unroll
    for (int i = K - 1; i >= 1; --i) {
        idx >>= 3;                                   // idx = r >> 3*(K-i)
        A += __ldg(xr + sj_loff(i) + idx) * (P * sj_invf(K - i));
        P *= ys[idx & 7];                            // fold digit d_{i-1}
    }
    return A + P * sj_invf(K);                       // i=0 term (pure exp), X_0=1
}

__global__ __launch_bounds__(256) void sigjoin8c_kernel(
    const float* __restrict__ x,   // [BATCH, SIGLEN]
    const float* __restrict__ y,   // [BATCH, 8]
    float* __restrict__ out)       // [BATCH, SIGLEN]
{
    const int b = blockIdx.y;
    __shared__ float ys[8];
    if (threadIdx.x < 8) ys[threadIdx.x] = y[b * SJ_D + threadIdx.x];
    __syncthreads();

    const int g = blockIdx.x * blockDim.x + threadIdx.x;  // group index
    if (g >= SJ_GROUPS) return;
    const int c = g * 8;                                  // first column of group

    const float* xr   = x   + (size_t)b * SJ_SIGLEN;
    float*       orow = out + (size_t)b * SJ_SIGLEN;

    // Bulk loads with DEFAULT cache policy (low levels are reused as prefixes).
    const float4 x0 = __ldg(reinterpret_cast<const float4*>(xr + c));
    const float4 x1 = __ldg(reinterpret_cast<const float4*>(xr + c + 4));

    // Level dispatch + shared prefix accumulator A (one per 8-group).
    float A;
    if (c >= 37448)      A = sj_chenA<6>(xr, ys, c - 37448);
    else if (c >= 4680)  A = sj_chenA<5>(xr, ys, c - 4680);
    else if (c >= 584)   A = sj_chenA<4>(xr, ys, c - 584);
    else if (c >= 72)    A = sj_chenA<3>(xr, ys, c - 72);
    else if (c >= 8)     A = sj_chenA<2>(xr, ys, c - 8);
    else                 A = 1.f;                         // level 1: z = x + y

    float4 z0, z1;
    z0.x = fmaf(A, ys[0], x0.x);
    z0.y = fmaf(A, ys[1], x0.y);
    z0.z = fmaf(A, ys[2], x0.z);
    z0.w = fmaf(A, ys[3], x0.w);
    z1.x = fmaf(A, ys[4], x1.x);
    z1.y = fmaf(A, ys[5], x1.y);
    z1.z = fmaf(A, ys[6], x1.z);
    z1.w = fmaf(A, ys[7], x1.w);

    // Output is never re-read: evict-first stores are correct here.
    __stcs(reinterpret_cast<float4*>(orow + c),     z0);
    __stcs(reinterpret_cast<float4*>(orow + c + 4), z1);
}

extern "C" void kernel_launch(void* const* d_in, const int* in_sizes, int n_in,
                              void* d_out, int out_size) {
    const float* x = (const float*)d_in[0];   // [128, 299592] fp32
    const float* y = (const float*)d_in[1];   // [128, 8] fp32
    float* out = (float*)d_out;

    dim3 block(256);
    dim3 grid((SJ_GROUPS + 255) / 256, SJ_BATCH);   // 147 x 128
    sigjoin8c_kernel<<<grid, block>>>(x, y, out);
}